// round 14
// baseline (speedup 1.0000x reference)
#include <cuda_runtime.h>
#include <cuda_fp16.h>
#include <cstdint>

// out = RowLocalAttn(v@Wq, v@Wk, v@Wv) @ Wp + bp
// v: [65536, 256] fp32. R14: R11 pipeline (64-wide K chunks, 3-stage cp.async)
// with 512 threads / 32x32 warp tiles: halves per-warp register footprint so
// 32 warps/SM fit -> 2x warps to hide ldsm->mma dependency latency.

#define M_TOTAL 65536
#define DIM     256

// ---------------- scratch ----------------------------------------------------
__device__ __align__(128) unsigned short g_vh[(size_t)M_TOTAL * DIM];       // fp16 v
__device__ __align__(128) unsigned short g_qkvh[(size_t)M_TOTAL * 3 * DIM]; // fp16 [M][768]
__device__ __align__(128) unsigned short g_xh[(size_t)M_TOTAL * DIM];       // fp16 x
__device__ __align__(128) unsigned short g_wqkv[768 * 256];                 // fp16 [n][k]
__device__ __align__(128) unsigned short g_wp[256 * 256];                   // fp16 [n][k]

// ---------------- PTX helpers ------------------------------------------------
__device__ __forceinline__ uint32_t smem_u32(const void* p) {
    uint32_t a;
    asm("{ .reg .u64 t; cvta.to.shared.u64 t, %1; cvt.u32.u64 %0, t; }" : "=r"(a) : "l"(p));
    return a;
}
__device__ __forceinline__ void cp_async16(uint32_t s, const void* g) {
    asm volatile("cp.async.cg.shared.global [%0], [%1], 16;" :: "r"(s), "l"(g));
}
__device__ __forceinline__ void cp_commit() { asm volatile("cp.async.commit_group;"); }
template<int N>
__device__ __forceinline__ void cp_wait() { asm volatile("cp.async.wait_group %0;" :: "n"(N)); }
__device__ __forceinline__ void ldsm4(uint32_t* r, uint32_t a) {
    asm volatile("ldmatrix.sync.aligned.m8n8.x4.shared.b16 {%0,%1,%2,%3}, [%4];"
        : "=r"(r[0]), "=r"(r[1]), "=r"(r[2]), "=r"(r[3]) : "r"(a));
}
__device__ __forceinline__ void mma16816(float* d, const uint32_t* a, const uint32_t* b) {
    asm volatile("mma.sync.aligned.m16n8k16.row.col.f32.f16.f16.f32 "
        "{%0,%1,%2,%3}, {%4,%5,%6,%7}, {%8,%9}, {%0,%1,%2,%3};"
        : "+f"(d[0]), "+f"(d[1]), "+f"(d[2]), "+f"(d[3])
        : "r"(a[0]), "r"(a[1]), "r"(a[2]), "r"(a[3]), "r"(b[0]), "r"(b[1]));
}
// swizzled offset in an N-row x 128-byte tile (16B granules, 8 per row)
__device__ __forceinline__ uint32_t swz8(int row, int c) {
    return (uint32_t)(row * 128 + ((c ^ (row & 7)) << 4));
}

// ---------------- fused v-convert + weight conversion ------------------------
__global__ __launch_bounds__(256)
void prep_kernel(const float4* __restrict__ vin, uint2* __restrict__ vh,
                 const float* __restrict__ Wq, const float* __restrict__ Wk,
                 const float* __restrict__ Wv, const float* __restrict__ Wp,
                 unsigned short* __restrict__ wqkv, unsigned short* __restrict__ wp)
{
    int bid = blockIdx.x;
    if (bid < 16384) {
        int i = bid * 256 + threadIdx.x;
        float4 f = vin[i];
        __half2 p0 = __floats2half2_rn(f.x, f.y);
        __half2 p1 = __floats2half2_rn(f.z, f.w);
        uint2 o;
        o.x = *(uint32_t*)&p0;
        o.y = *(uint32_t*)&p1;
        vh[i] = o;
    } else {
        int idx = bid - 16384;
        int wi = idx >> 8;
        int n  = idx & 255;
        int k  = threadIdx.x;
        const float* W = (wi == 0) ? Wq : (wi == 1) ? Wk : (wi == 2) ? Wv : Wp;
        __half h = __float2half_rn(W[k * 256 + n]);
        if (wi < 3)
            wqkv[(size_t)(wi * 256 + n) * 256 + k] = *(unsigned short*)&h;
        else
            wp[(size_t)n * 256 + k] = *(unsigned short*)&h;
    }
}

// ---------------- fp16 GEMM, 64-wide K chunks, 3-stage cp.async --------------
// 512 threads, 16 warps in 4x4 grid, warp tile 32(M)x32(N).
// C[by*128..+128][bx*128..+128] = A @ B^T (+bias).
static constexpr int STAGE_BYTES = 32768;          // A 16K | B 16K
static constexpr int OFF_A = 0, OFF_B = 16384;
static constexpr int GEMM_SMEM = 3 * STAGE_BYTES;  // 98304

template<bool HALF_OUT, bool BIAS>
__global__ __launch_bounds__(512, 2)
void gemm_kernel(const unsigned short* __restrict__ A,
                 const unsigned short* __restrict__ B,
                 const float* __restrict__ bias, void* __restrict__ Cv, int ldc)
{
    extern __shared__ char smem[];
    const uint32_t sb = smem_u32(smem);
    const int tid  = threadIdx.x;
    const int wid  = tid >> 5;
    const int lane = tid & 31;
    const int mw = wid & 3;        // 4 warp rows (32 each)
    const int nw = wid >> 2;       // 4 warp cols (32 each)

    const int mbase = blockIdx.y * 128;
    const int nbase = blockIdx.x * 128;

    // one 64-wide K chunk: A 128x64 fp16 (16KB) + B 128x64 fp16 (16KB)
    auto load_chunk = [&](int kc, int s) {
        const uint32_t stg = sb + s * STAGE_BYTES;
        #pragma unroll
        for (int i = 0; i < 2; i++) {
            int u = tid + i * 512;             // 1024 granules per 16K tile
            int row = u >> 3, c = u & 7;
            uint32_t so = swz8(row, c);
            size_t ga = (size_t)(mbase + row) * 256 + kc * 64 + c * 8;
            size_t gb = (size_t)(nbase + row) * 256 + kc * 64 + c * 8;
            cp_async16(stg + OFF_A + so, A + ga);
            cp_async16(stg + OFF_B + so, B + gb);
        }
        cp_commit();
    };

    float acc[2][4][4];
    #pragma unroll
    for (int i = 0; i < 2; i++)
        #pragma unroll
        for (int j = 0; j < 4; j++)
            #pragma unroll
            for (int r = 0; r < 4; r++) acc[i][j][r] = 0.0f;

    load_chunk(0, 0);
    load_chunk(1, 1);

    for (int kc = 0; kc < 4; kc++) {
        if (kc == 3) cp_wait<0>(); else cp_wait<1>();
        __syncthreads();
        if (kc < 2) load_chunk(kc + 2, (kc + 2) % 3);

        const uint32_t stg = sb + (kc % 3) * STAGE_BYTES;
        #pragma unroll
        for (int ks = 0; ks < 4; ks++) {           // 4 k16 slices per chunk
            uint32_t a_f[2][4];
            {
                int ar = mw * 32 + (lane & 15);
                int ac = ks * 2 + (lane >> 4);
                #pragma unroll
                for (int mt = 0; mt < 2; mt++)
                    ldsm4(a_f[mt], stg + OFF_A + swz8(ar + mt * 16, ac));
            }
            uint32_t b_f[4][2];
            {
                int nr0 = nw * 32 + ((lane >> 4) << 3) + (lane & 7);
                int bc  = ks * 2 + ((lane >> 3) & 1);
                #pragma unroll
                for (int nh = 0; nh < 2; nh++) {
                    uint32_t r[4];
                    ldsm4(r, stg + OFF_B + swz8(nr0 + nh * 16, bc));
                    b_f[nh * 2][0] = r[0]; b_f[nh * 2][1] = r[1];
                    b_f[nh * 2 + 1][0] = r[2]; b_f[nh * 2 + 1][1] = r[3];
                }
            }
            #pragma unroll
            for (int mt = 0; mt < 2; mt++)
                #pragma unroll
                for (int nt = 0; nt < 4; nt++)
                    mma16816(acc[mt][nt], a_f[mt], b_f[nt]);
        }
    }

    if (HALF_OUT) {
        __half* C = (__half*)Cv;
        #pragma unroll
        for (int mt = 0; mt < 2; mt++) {
            int r0 = mbase + mw * 32 + mt * 16 + (lane >> 2);
            #pragma unroll
            for (int nt = 0; nt < 4; nt++) {
                int col = nbase + nw * 32 + nt * 8 + (lane & 3) * 2;
                __half2 h0 = __floats2half2_rn(acc[mt][nt][0], acc[mt][nt][1]);
                __half2 h1 = __floats2half2_rn(acc[mt][nt][2], acc[mt][nt][3]);
                *(uint32_t*)(C + (size_t)r0 * ldc + col)       = *(uint32_t*)&h0;
                *(uint32_t*)(C + (size_t)(r0 + 8) * ldc + col) = *(uint32_t*)&h1;
            }
        }
    } else {
        float* C = (float*)Cv;
        #pragma unroll
        for (int mt = 0; mt < 2; mt++) {
            int r0 = mbase + mw * 32 + mt * 16 + (lane >> 2);
            #pragma unroll
            for (int nt = 0; nt < 4; nt++) {
                int col = nbase + nw * 32 + nt * 8 + (lane & 3) * 2;
                float b0 = 0.f, b1 = 0.f;
                if (BIAS) { b0 = bias[col]; b1 = bias[col + 1]; }
                *(float2*)(C + (size_t)r0 * ldc + col) =
                    make_float2(acc[mt][nt][0] + b0, acc[mt][nt][1] + b1);
                *(float2*)(C + (size_t)(r0 + 8) * ldc + col) =
                    make_float2(acc[mt][nt][2] + b0, acc[mt][nt][3] + b1);
            }
        }
    }
}

// ---------------- row-local attention (fp16 qkv in, fp16 x out) --------------
#define ROWH 776
static constexpr int ATTN_SMEM = 32 * ROWH * 2;   // 49664 B

__global__ __launch_bounds__(256, 4)
void attn_kernel(const __half* __restrict__ qkv, unsigned short* __restrict__ xh)
{
    extern __shared__ __half sh[];
    const uint32_t sb = smem_u32(sh);
    const int row0 = blockIdx.x * 32;
    const int tid  = threadIdx.x;

    #pragma unroll
    for (int i = 0; i < 12; i++) {
        int u = tid + 256 * i;
        int r = u / 96, c = u % 96;
        cp_async16(sb + (uint32_t)(r * 97 + c) * 16,
                   (const uint4*)qkv + (size_t)(row0 + r) * 96 + c);
    }
    cp_commit();
    cp_wait<0>();
    __syncthreads();

    const int r = tid >> 3;
    const int h = tid & 7;
    const __half2* q2 = (const __half2*)(sh + r * ROWH + h * 32);
    const __half2* k2 = (const __half2*)(sh + r * ROWH + 256);
    const __half2* v2 = (const __half2*)(sh + r * ROWH + 512);

    float q[32];
    #pragma unroll
    for (int i = 0; i < 16; i++) {
        float2 f = __half22float2(q2[i]);
        q[2 * i] = f.x; q[2 * i + 1] = f.y;
    }

    const float scale = 0.17677669529663687f;  // 1/sqrt(32)

    float p[8];
    #pragma unroll
    for (int g = 0; g < 8; g++) p[g] = 0.0f;
    #pragma unroll
    for (int d2 = 0; d2 < 16; d2++) {
        float qx = q[2 * d2], qy = q[2 * d2 + 1];
        #pragma unroll
        for (int g = 0; g < 8; g++) {
            float2 kk = __half22float2(k2[g * 16 + d2]);
            p[g] = fmaf(qx, kk.x, fmaf(qy, kk.y, p[g]));
        }
    }
    float mx = p[0] * scale;
    #pragma unroll
    for (int g = 1; g < 8; g++) mx = fmaxf(mx, p[g] * scale);
    float sum = 0.0f;
    #pragma unroll
    for (int g = 0; g < 8; g++) { p[g] = __expf(p[g] * scale - mx); sum += p[g]; }
    const float inv = 1.0f / sum;
    #pragma unroll
    for (int g = 0; g < 8; g++) p[g] *= inv;

    size_t base = (size_t)(row0 + r) * 256 + h * 32;
    #pragma unroll
    for (int cb = 0; cb < 4; cb++) {
        uint32_t obuf[4];
        #pragma unroll
        for (int dd2 = 0; dd2 < 4; dd2++) {
            int d2 = cb * 4 + dd2;
            float ax = 0.0f, ay = 0.0f;
            #pragma unroll
            for (int g = 0; g < 8; g++) {
                float2 vvv = __half22float2(v2[g * 16 + d2]);
                ax = fmaf(p[g], vvv.x, ax);
                ay = fmaf(p[g], vvv.y, ay);
            }
            __half2 hh = __floats2half2_rn(ax, ay);
            obuf[dd2] = *(uint32_t*)&hh;
        }
        *(uint4*)(xh + base + cb * 8) = *(uint4*)obuf;
    }
}

// ---------------- launch ------------------------------------------------------
extern "C" void kernel_launch(void* const* d_in, const int* in_sizes, int n_in,
                              void* d_out, int out_size)
{
    const float* v  = (const float*)d_in[0];
    const float* Wq = (const float*)d_in[1];
    const float* Wk = (const float*)d_in[2];
    const float* Wv = (const float*)d_in[3];
    const float* Wp = (const float*)d_in[4];
    const float* bp = (const float*)d_in[5];
    float* out = (float*)d_out;

    unsigned short *vh, *xh, *wqkv, *wp, *qkvh;
    cudaGetSymbolAddress((void**)&vh,   g_vh);
    cudaGetSymbolAddress((void**)&xh,   g_xh);
    cudaGetSymbolAddress((void**)&wqkv, g_wqkv);
    cudaGetSymbolAddress((void**)&wp,   g_wp);
    cudaGetSymbolAddress((void**)&qkvh, g_qkvh);

    cudaFuncSetAttribute((const void*)gemm_kernel<true, false>,
                         cudaFuncAttributeMaxDynamicSharedMemorySize, GEMM_SMEM);
    cudaFuncSetAttribute((const void*)gemm_kernel<false, true>,
                         cudaFuncAttributeMaxDynamicSharedMemorySize, GEMM_SMEM);
    cudaFuncSetAttribute((const void*)attn_kernel,
                         cudaFuncAttributeMaxDynamicSharedMemorySize, ATTN_SMEM);

    // fused v-convert + weight conversion
    prep_kernel<<<16384 + 1024, 256>>>((const float4*)v, (uint2*)vh,
                                       Wq, Wk, Wv, Wp, wqkv, wp);

    // merged QKV projection: N = 768, fp16 output
    dim3 gq(6, M_TOTAL / 128);
    gemm_kernel<true, false><<<gq, 512, GEMM_SMEM>>>(vh, wqkv, nullptr, qkvh, 768);

    // attention: fp16 qkv -> fp16 x
    attn_kernel<<<M_TOTAL / 32, 256, ATTN_SMEM>>>((const __half*)qkvh, xh);

    // output projection + bias (fp32 out)
    dim3 gp(2, M_TOTAL / 128);
    gemm_kernel<false, true><<<gp, 512, GEMM_SMEM>>>(xh, wp, bp, out, DIM);
}

// round 15
// speedup vs baseline: 1.2199x; 1.2199x over previous
#include <cuda_runtime.h>
#include <cuda_fp16.h>
#include <cstdint>

// out = RowLocalAttn(v@Wq, v@Wk, v@Wv) @ Wp + bp
// v: [65536, 256] fp32. R15: R11 kernel (fp16 mma.sync, 64-wide K chunks,
// 3-stage cp.async, 256 thr, 64x32 warp tiles) + per-warp ks phase-stagger:
// warps start the 4 k16-slices at different offsets so ldsm and mma phases
// overlap across warps instead of locking step after each __syncthreads.

#define M_TOTAL 65536
#define DIM     256

// ---------------- scratch ----------------------------------------------------
__device__ __align__(128) unsigned short g_vh[(size_t)M_TOTAL * DIM];       // fp16 v
__device__ __align__(128) unsigned short g_qkvh[(size_t)M_TOTAL * 3 * DIM]; // fp16 [M][768]
__device__ __align__(128) unsigned short g_xh[(size_t)M_TOTAL * DIM];       // fp16 x
__device__ __align__(128) unsigned short g_wqkv[768 * 256];                 // fp16 [n][k]
__device__ __align__(128) unsigned short g_wp[256 * 256];                   // fp16 [n][k]

// ---------------- PTX helpers ------------------------------------------------
__device__ __forceinline__ uint32_t smem_u32(const void* p) {
    uint32_t a;
    asm("{ .reg .u64 t; cvta.to.shared.u64 t, %1; cvt.u32.u64 %0, t; }" : "=r"(a) : "l"(p));
    return a;
}
__device__ __forceinline__ void cp_async16(uint32_t s, const void* g) {
    asm volatile("cp.async.cg.shared.global [%0], [%1], 16;" :: "r"(s), "l"(g));
}
__device__ __forceinline__ void cp_commit() { asm volatile("cp.async.commit_group;"); }
template<int N>
__device__ __forceinline__ void cp_wait() { asm volatile("cp.async.wait_group %0;" :: "n"(N)); }
__device__ __forceinline__ void ldsm4(uint32_t* r, uint32_t a) {
    asm volatile("ldmatrix.sync.aligned.m8n8.x4.shared.b16 {%0,%1,%2,%3}, [%4];"
        : "=r"(r[0]), "=r"(r[1]), "=r"(r[2]), "=r"(r[3]) : "r"(a));
}
__device__ __forceinline__ void mma16816(float* d, const uint32_t* a, const uint32_t* b) {
    asm volatile("mma.sync.aligned.m16n8k16.row.col.f32.f16.f16.f32 "
        "{%0,%1,%2,%3}, {%4,%5,%6,%7}, {%8,%9}, {%0,%1,%2,%3};"
        : "+f"(d[0]), "+f"(d[1]), "+f"(d[2]), "+f"(d[3])
        : "r"(a[0]), "r"(a[1]), "r"(a[2]), "r"(a[3]), "r"(b[0]), "r"(b[1]));
}
// swizzled offset in an N-row x 128-byte tile (16B granules, 8 per row)
__device__ __forceinline__ uint32_t swz8(int row, int c) {
    return (uint32_t)(row * 128 + ((c ^ (row & 7)) << 4));
}

// ---------------- fused v-convert + weight conversion ------------------------
__global__ __launch_bounds__(256)
void prep_kernel(const float4* __restrict__ vin, uint2* __restrict__ vh,
                 const float* __restrict__ Wq, const float* __restrict__ Wk,
                 const float* __restrict__ Wv, const float* __restrict__ Wp,
                 unsigned short* __restrict__ wqkv, unsigned short* __restrict__ wp)
{
    int bid = blockIdx.x;
    if (bid < 16384) {
        int i = bid * 256 + threadIdx.x;
        float4 f = vin[i];
        __half2 p0 = __floats2half2_rn(f.x, f.y);
        __half2 p1 = __floats2half2_rn(f.z, f.w);
        uint2 o;
        o.x = *(uint32_t*)&p0;
        o.y = *(uint32_t*)&p1;
        vh[i] = o;
    } else {
        int idx = bid - 16384;
        int wi = idx >> 8;
        int n  = idx & 255;
        int k  = threadIdx.x;
        const float* W = (wi == 0) ? Wq : (wi == 1) ? Wk : (wi == 2) ? Wv : Wp;
        __half h = __float2half_rn(W[k * 256 + n]);
        if (wi < 3)
            wqkv[(size_t)(wi * 256 + n) * 256 + k] = *(unsigned short*)&h;
        else
            wp[(size_t)n * 256 + k] = *(unsigned short*)&h;
    }
}

// ---------------- fp16 GEMM, 64-wide K chunks, 3-stage cp.async --------------
// 256 threads, 8 warps in 2x4 grid, warp tile 64(M)x32(N). ks phase-staggered.
static constexpr int STAGE_BYTES = 32768;          // A 16K | B 16K
static constexpr int OFF_A = 0, OFF_B = 16384;
static constexpr int GEMM_SMEM = 3 * STAGE_BYTES;  // 98304

template<bool HALF_OUT, bool BIAS>
__global__ __launch_bounds__(256)
void gemm_kernel(const unsigned short* __restrict__ A,
                 const unsigned short* __restrict__ B,
                 const float* __restrict__ bias, void* __restrict__ Cv, int ldc)
{
    extern __shared__ char smem[];
    const uint32_t sb = smem_u32(smem);
    const int tid  = threadIdx.x;
    const int wid  = tid >> 5;
    const int lane = tid & 31;
    const int mw = wid & 1;        // 2 warp rows (64 each)
    const int nw = wid >> 1;       // 4 warp cols (32 each)
    const int kphase = wid & 3;    // per-warp ks start offset

    const int mbase = blockIdx.y * 128;
    const int nbase = blockIdx.x * 128;

    // one 64-wide K chunk: A 128x64 fp16 (16KB) + B 128x64 fp16 (16KB)
    auto load_chunk = [&](int kc, int s) {
        const uint32_t stg = sb + s * STAGE_BYTES;
        #pragma unroll
        for (int i = 0; i < 4; i++) {
            int u = tid + i * 256;             // 1024 granules per 16K tile
            int row = u >> 3, c = u & 7;
            uint32_t so = swz8(row, c);
            size_t ga = (size_t)(mbase + row) * 256 + kc * 64 + c * 8;
            size_t gb = (size_t)(nbase + row) * 256 + kc * 64 + c * 8;
            cp_async16(stg + OFF_A + so, A + ga);
            cp_async16(stg + OFF_B + so, B + gb);
        }
        cp_commit();
    };

    float acc[4][4][4];
    #pragma unroll
    for (int i = 0; i < 4; i++)
        #pragma unroll
        for (int j = 0; j < 4; j++)
            #pragma unroll
            for (int r = 0; r < 4; r++) acc[i][j][r] = 0.0f;

    load_chunk(0, 0);
    load_chunk(1, 1);

    for (int kc = 0; kc < 4; kc++) {
        if (kc == 3) cp_wait<0>(); else cp_wait<1>();
        __syncthreads();
        if (kc < 2) load_chunk(kc + 2, (kc + 2) % 3);

        const uint32_t stg = sb + (kc % 3) * STAGE_BYTES;
        #pragma unroll
        for (int kss = 0; kss < 4; kss++) {        // staggered k16 slices
            const int ks = (kss + kphase) & 3;
            uint32_t a_f[4][4];
            {
                int ar = mw * 64 + (lane & 15);
                int ac = ks * 2 + (lane >> 4);
                #pragma unroll
                for (int mt = 0; mt < 4; mt++)
                    ldsm4(a_f[mt], stg + OFF_A + swz8(ar + mt * 16, ac));
            }
            uint32_t b_f[4][2];
            {
                int nr0 = nw * 32 + ((lane >> 4) << 3) + (lane & 7);
                int bc  = ks * 2 + ((lane >> 3) & 1);
                #pragma unroll
                for (int nh = 0; nh < 2; nh++) {
                    uint32_t r[4];
                    ldsm4(r, stg + OFF_B + swz8(nr0 + nh * 16, bc));
                    b_f[nh * 2][0] = r[0]; b_f[nh * 2][1] = r[1];
                    b_f[nh * 2 + 1][0] = r[2]; b_f[nh * 2 + 1][1] = r[3];
                }
            }
            #pragma unroll
            for (int mt = 0; mt < 4; mt++)
                #pragma unroll
                for (int nt = 0; nt < 4; nt++)
                    mma16816(acc[mt][nt], a_f[mt], b_f[nt]);
        }
    }

    if (HALF_OUT) {
        __half* C = (__half*)Cv;
        #pragma unroll
        for (int mt = 0; mt < 4; mt++) {
            int r0 = mbase + mw * 64 + mt * 16 + (lane >> 2);
            #pragma unroll
            for (int nt = 0; nt < 4; nt++) {
                int col = nbase + nw * 32 + nt * 8 + (lane & 3) * 2;
                __half2 h0 = __floats2half2_rn(acc[mt][nt][0], acc[mt][nt][1]);
                __half2 h1 = __floats2half2_rn(acc[mt][nt][2], acc[mt][nt][3]);
                *(uint32_t*)(C + (size_t)r0 * ldc + col)       = *(uint32_t*)&h0;
                *(uint32_t*)(C + (size_t)(r0 + 8) * ldc + col) = *(uint32_t*)&h1;
            }
        }
    } else {
        float* C = (float*)Cv;
        #pragma unroll
        for (int mt = 0; mt < 4; mt++) {
            int r0 = mbase + mw * 64 + mt * 16 + (lane >> 2);
            #pragma unroll
            for (int nt = 0; nt < 4; nt++) {
                int col = nbase + nw * 32 + nt * 8 + (lane & 3) * 2;
                float b0 = 0.f, b1 = 0.f;
                if (BIAS) { b0 = bias[col]; b1 = bias[col + 1]; }
                *(float2*)(C + (size_t)r0 * ldc + col) =
                    make_float2(acc[mt][nt][0] + b0, acc[mt][nt][1] + b1);
                *(float2*)(C + (size_t)(r0 + 8) * ldc + col) =
                    make_float2(acc[mt][nt][2] + b0, acc[mt][nt][3] + b1);
            }
        }
    }
}

// ---------------- row-local attention (fp16 qkv in, fp16 x out) --------------
#define ROWH 776
static constexpr int ATTN_SMEM = 32 * ROWH * 2;   // 49664 B

__global__ __launch_bounds__(256, 4)
void attn_kernel(const __half* __restrict__ qkv, unsigned short* __restrict__ xh)
{
    extern __shared__ __half sh[];
    const uint32_t sb = smem_u32(sh);
    const int row0 = blockIdx.x * 32;
    const int tid  = threadIdx.x;

    #pragma unroll
    for (int i = 0; i < 12; i++) {
        int u = tid + 256 * i;
        int r = u / 96, c = u % 96;
        cp_async16(sb + (uint32_t)(r * 97 + c) * 16,
                   (const uint4*)qkv + (size_t)(row0 + r) * 96 + c);
    }
    cp_commit();
    cp_wait<0>();
    __syncthreads();

    const int r = tid >> 3;
    const int h = tid & 7;
    const __half2* q2 = (const __half2*)(sh + r * ROWH + h * 32);
    const __half2* k2 = (const __half2*)(sh + r * ROWH + 256);
    const __half2* v2 = (const __half2*)(sh + r * ROWH + 512);

    float q[32];
    #pragma unroll
    for (int i = 0; i < 16; i++) {
        float2 f = __half22float2(q2[i]);
        q[2 * i] = f.x; q[2 * i + 1] = f.y;
    }

    const float scale = 0.17677669529663687f;  // 1/sqrt(32)

    float p[8];
    #pragma unroll
    for (int g = 0; g < 8; g++) p[g] = 0.0f;
    #pragma unroll
    for (int d2 = 0; d2 < 16; d2++) {
        float qx = q[2 * d2], qy = q[2 * d2 + 1];
        #pragma unroll
        for (int g = 0; g < 8; g++) {
            float2 kk = __half22float2(k2[g * 16 + d2]);
            p[g] = fmaf(qx, kk.x, fmaf(qy, kk.y, p[g]));
        }
    }
    float mx = p[0] * scale;
    #pragma unroll
    for (int g = 1; g < 8; g++) mx = fmaxf(mx, p[g] * scale);
    float sum = 0.0f;
    #pragma unroll
    for (int g = 0; g < 8; g++) { p[g] = __expf(p[g] * scale - mx); sum += p[g]; }
    const float inv = 1.0f / sum;
    #pragma unroll
    for (int g = 0; g < 8; g++) p[g] *= inv;

    size_t base = (size_t)(row0 + r) * 256 + h * 32;
    #pragma unroll
    for (int cb = 0; cb < 4; cb++) {
        uint32_t obuf[4];
        #pragma unroll
        for (int dd2 = 0; dd2 < 4; dd2++) {
            int d2 = cb * 4 + dd2;
            float ax = 0.0f, ay = 0.0f;
            #pragma unroll
            for (int g = 0; g < 8; g++) {
                float2 vvv = __half22float2(v2[g * 16 + d2]);
                ax = fmaf(p[g], vvv.x, ax);
                ay = fmaf(p[g], vvv.y, ay);
            }
            __half2 hh = __floats2half2_rn(ax, ay);
            obuf[dd2] = *(uint32_t*)&hh;
        }
        *(uint4*)(xh + base + cb * 8) = *(uint4*)obuf;
    }
}

// ---------------- launch ------------------------------------------------------
extern "C" void kernel_launch(void* const* d_in, const int* in_sizes, int n_in,
                              void* d_out, int out_size)
{
    const float* v  = (const float*)d_in[0];
    const float* Wq = (const float*)d_in[1];
    const float* Wk = (const float*)d_in[2];
    const float* Wv = (const float*)d_in[3];
    const float* Wp = (const float*)d_in[4];
    const float* bp = (const float*)d_in[5];
    float* out = (float*)d_out;

    unsigned short *vh, *xh, *wqkv, *wp, *qkvh;
    cudaGetSymbolAddress((void**)&vh,   g_vh);
    cudaGetSymbolAddress((void**)&xh,   g_xh);
    cudaGetSymbolAddress((void**)&wqkv, g_wqkv);
    cudaGetSymbolAddress((void**)&wp,   g_wp);
    cudaGetSymbolAddress((void**)&qkvh, g_qkvh);

    cudaFuncSetAttribute((const void*)gemm_kernel<true, false>,
                         cudaFuncAttributeMaxDynamicSharedMemorySize, GEMM_SMEM);
    cudaFuncSetAttribute((const void*)gemm_kernel<false, true>,
                         cudaFuncAttributeMaxDynamicSharedMemorySize, GEMM_SMEM);
    cudaFuncSetAttribute((const void*)attn_kernel,
                         cudaFuncAttributeMaxDynamicSharedMemorySize, ATTN_SMEM);

    // fused v-convert + weight conversion
    prep_kernel<<<16384 + 1024, 256>>>((const float4*)v, (uint2*)vh,
                                       Wq, Wk, Wv, Wp, wqkv, wp);

    // merged QKV projection: N = 768, fp16 output
    dim3 gq(6, M_TOTAL / 128);
    gemm_kernel<true, false><<<gq, 256, GEMM_SMEM>>>(vh, wqkv, nullptr, qkvh, 768);

    // attention: fp16 qkv -> fp16 x
    attn_kernel<<<M_TOTAL / 32, 256, ATTN_SMEM>>>((const __half*)qkvh, xh);

    // output projection + bias (fp32 out)
    dim3 gp(2, M_TOTAL / 128);
    gemm_kernel<false, true><<<gp, 256, GEMM_SMEM>>>(xh, wp, bp, out, DIM);
}